// round 15
// baseline (speedup 1.0000x reference)
#include <cuda_runtime.h>

// MaxUnpool2D: B=8, H=W=128, C=64, KH=KW=2, HOUT=WOUT=256.
// Mask guarantees each input element's target lies inside its own disjoint 2x2
// output window => unique targets (plain stores), windows tile the output
// exactly (no zero-fill pass).
//
// Round 14: attack steady-state dirty-writeback contention. All prior cache
// hints left output lines DIRTY in L2, so every graph replay starts by
// draining 134 MB of writeback debt before its reads/allocations proceed.
// __stwt (write-through) stores push output to DRAM at store time and leave
// L2 lines CLEAN: zero writeback debt across replays, free evictions, read
// stream never serializes behind a dirty-victim drain. Same 201 MB/iter
// total DRAM traffic, better overlap.

#define B_    8
#define H_    128
#define W_    128
#define C_    64
#define HOUT_ 256
#define WOUT_ 256
#define C4_   16                       // float4 groups per pixel
#define N4_   (B_ * H_ * W_ * C4_)     // 2,097,152 float4 elements

__global__ void __launch_bounds__(256)
max_unpool_kernel(const float4* __restrict__ x4,
                  const int4*   __restrict__ m4,
                  float4*       __restrict__ out4)
{
    const int t = blockIdx.x * 256 + threadIdx.x;

    // Default-priority loads (proven fastest load path).
    const float4 v = x4[t];
    const int4   m = m4[t];

    // t layout: (((b*H + h)*W + w) * C4 + c4)
    const int c4 = t & (C4_ - 1);
    const int w  = (t >> 4) & (W_ - 1);
    const int h  = (t >> 11) & (H_ - 1);
    const int b  = t >> 18;

    // Flat per-batch element index of channel c4*4 at window pos (0,0).
    const int p00   = (h * 2 * WOUT_ + w * 2) * C_ + c4 * 4;
    const int base4 = b * (HOUT_ * WOUT_ * C4_) + (p00 >> 2);

    const float vx[4] = {v.x, v.y, v.z, v.w};
    const int   mi[4] = {m.x, m.y, m.z, m.w};

#pragma unroll
    for (int dh = 0; dh < 2; ++dh) {
#pragma unroll
        for (int dw = 0; dw < 2; ++dw) {
            const int p = p00 + dh * (WOUT_ * C_) + dw * C_;
            float4 o;
            o.x = (mi[0] == p + 0) ? vx[0] : 0.0f;
            o.y = (mi[1] == p + 1) ? vx[1] : 0.0f;
            o.z = (mi[2] == p + 2) ? vx[2] : 0.0f;
            o.w = (mi[3] == p + 3) ? vx[3] : 0.0f;
            // Write-through: output reaches DRAM now; L2 line stays clean,
            // so no writeback debt survives into the next graph replay.
            __stwt(out4 + base4 + dh * (WOUT_ * C4_) + dw * C4_, o);
        }
    }
}

extern "C" void kernel_launch(void* const* d_in, const int* in_sizes, int n_in,
                              void* d_out, int out_size)
{
    const float4* x4 = (const float4*)d_in[0];  // input_pool f32 [8,128,128,64]
    const int4*   m4 = (const int4*)d_in[1];    // pool_mask  i32 [8,128,128,64]
    float4* out4 = (float4*)d_out;              // [8,256,256,64] f32

    const int block = 256;
    const int grid  = N4_ / block;              // 8192 blocks
    max_unpool_kernel<<<grid, block>>>(x4, m4, out4);
}